// round 3
// baseline (speedup 1.0000x reference)
#include <cuda_runtime.h>
#include <math.h>

#define FIXED_FRAMES 30
#define N_SEL 107
#define N_LM 543
#define RED_BLOCKS 1184
#define RED_THREADS 256
#define N_GATHER 30          // last N_GATHER ticketed blocks gather one frame each

__constant__ int c_sel[N_SEL] = {
    61,185,40,39,37,0,267,269,270,409,291,
    146,91,181,84,17,314,405,321,375,
    78,191,80,81,82,13,312,311,310,415,
    95,88,178,87,14,317,402,318,324,308,
    468,469,470,471,472,473,474,475,476,477,478,479,480,481,482,483,484,485,486,487,488,
    489,490,491,492,493,494,495,496,497,498,499,500,501,502,503,504,505,506,507,508,509,510,511,512,513,
    522,523,524,525,526,527,528,529,530,531,532,533,534,535,536,537,538,539,540,541,542
};

// Per-block partials (written unconditionally every launch — no init needed)
__device__ float g_psum[RED_BLOCKS];
__device__ float g_psumsq[RED_BLOCKS];
__device__ int   g_pcnt[RED_BLOCKS];
// Completion protocol state; reset to 0 at the end of every launch.
__device__ int g_done = 0;
__device__ int g_ack  = 0;

__global__ void __launch_bounds__(RED_THREADS) fused_kernel(
        const float4* __restrict__ xv, long long nvec,
        const float* __restrict__ x, long long ntail,
        float* __restrict__ out, int T) {
    // ---------------- Phase 1: nan-aware streaming reduction ----------------
    float s = 0.0f, q = 0.0f;
    int cnt = 0;

    const long long stride = (long long)gridDim.x * blockDim.x;
    long long i = (long long)blockIdx.x * blockDim.x + threadIdx.x;

    #define ACC(v) { \
        float t0 = (v.x == v.x) ? v.x : 0.0f; cnt += (v.x == v.x); \
        float t1 = (v.y == v.y) ? v.y : 0.0f; cnt += (v.y == v.y); \
        float t2 = (v.z == v.z) ? v.z : 0.0f; cnt += (v.z == v.z); \
        float t3 = (v.w == v.w) ? v.w : 0.0f; cnt += (v.w == v.w); \
        s += t0 + t1 + t2 + t3; \
        q += t0*t0 + t1*t1 + t2*t2 + t3*t3; }

    for (; i + 7 * stride < nvec; i += 8 * stride) {
        float4 a0 = xv[i];
        float4 a1 = xv[i + stride];
        float4 a2 = xv[i + 2 * stride];
        float4 a3 = xv[i + 3 * stride];
        float4 a4 = xv[i + 4 * stride];
        float4 a5 = xv[i + 5 * stride];
        float4 a6 = xv[i + 6 * stride];
        float4 a7 = xv[i + 7 * stride];
        ACC(a0); ACC(a1); ACC(a2); ACC(a3);
        ACC(a4); ACC(a5); ACC(a6); ACC(a7);
    }
    for (; i < nvec; i += stride) {
        float4 a = xv[i];
        ACC(a);
    }
    #undef ACC

    if (blockIdx.x == 0 && threadIdx.x == 0) {
        for (long long t = nvec * 4; t < nvec * 4 + ntail; t++) {
            float v = x[t];
            if (v == v) { s += v; q += v * v; cnt += 1; }
        }
    }

    // block-level reduce
    for (int off = 16; off; off >>= 1) {
        s   += __shfl_down_sync(0xFFFFFFFFu, s, off);
        q   += __shfl_down_sync(0xFFFFFFFFu, q, off);
        cnt += __shfl_down_sync(0xFFFFFFFFu, cnt, off);
    }
    __shared__ float ss[8], sq[8];
    __shared__ int sc[8];
    int wid = threadIdx.x >> 5;
    int lid = threadIdx.x & 31;
    if (lid == 0) { ss[wid] = s; sq[wid] = q; sc[wid] = cnt; }
    __syncthreads();
    __shared__ int s_ticket;
    if (wid == 0) {
        s   = (lid < (RED_THREADS >> 5)) ? ss[lid] : 0.0f;
        q   = (lid < (RED_THREADS >> 5)) ? sq[lid] : 0.0f;
        cnt = (lid < (RED_THREADS >> 5)) ? sc[lid] : 0;
        for (int off = 4; off; off >>= 1) {
            s   += __shfl_down_sync(0xFFFFFFFFu, s, off);
            q   += __shfl_down_sync(0xFFFFFFFFu, q, off);
            cnt += __shfl_down_sync(0xFFFFFFFFu, cnt, off);
        }
        if (lid == 0) {
            g_psum[blockIdx.x]   = s;
            g_psumsq[blockIdx.x] = q;
            g_pcnt[blockIdx.x]   = cnt;
            __threadfence();                        // publish partials
            s_ticket = atomicAdd(&g_done, 1);       // take ticket
        }
    }
    __syncthreads();
    int ticket = s_ticket;
    if (ticket < RED_BLOCKS - N_GATHER) return;     // non-gather blocks exit

    // ---------------- Phase 2: wait for all partials ----------------
    if (threadIdx.x == 0) {
        while (*(volatile int*)&g_done < RED_BLOCKS) __nanosleep(64);
        __threadfence();                            // order subsequent reads
        atomicAdd(&g_ack, 1);                       // signal observation
    }
    __syncthreads();

    // ---------------- Phase 3: final stats (redundant per gather block) -----
    __shared__ double r_s[8], r_q[8];
    __shared__ long long r_c[8];
    __shared__ float s_mean, s_invstd;
    {
        double ds = 0.0, dq = 0.0;
        long long dc = 0;
        for (int t = threadIdx.x; t < RED_BLOCKS; t += RED_THREADS) {
            ds += (double)g_psum[t];
            dq += (double)g_psumsq[t];
            dc += (long long)g_pcnt[t];
        }
        for (int off = 16; off; off >>= 1) {
            ds += __shfl_down_sync(0xFFFFFFFFu, ds, off);
            dq += __shfl_down_sync(0xFFFFFFFFu, dq, off);
            dc += __shfl_down_sync(0xFFFFFFFFu, dc, off);
        }
        if (lid == 0) { r_s[wid] = ds; r_q[wid] = dq; r_c[wid] = dc; }
        __syncthreads();
        if (wid == 0) {
            ds = (lid < (RED_THREADS >> 5)) ? r_s[lid] : 0.0;
            dq = (lid < (RED_THREADS >> 5)) ? r_q[lid] : 0.0;
            dc = (lid < (RED_THREADS >> 5)) ? r_c[lid] : 0;
            for (int off = 4; off; off >>= 1) {
                ds += __shfl_down_sync(0xFFFFFFFFu, ds, off);
                dq += __shfl_down_sync(0xFFFFFFFFu, dq, off);
                dc += __shfl_down_sync(0xFFFFFFFFu, dc, off);
            }
            if (lid == 0) {
                double cn = (double)dc;
                double mean = ds / cn;
                double var = (dq - ds * ds / cn) / (cn - 1.0);
                s_mean = (float)mean;
                s_invstd = (float)(1.0 / sqrt(var));
            }
        }
        __syncthreads();
    }
    float meanf = s_mean;
    float inv_std = s_invstd;

    // ---------------- Phase 4: gather this block's frame ----------------
    int f = ticket - (RED_BLOCKS - N_GATHER);       // 0..29
    if (T >= FIXED_FRAMES) {
        // nearest-exact (f32 arithmetic matching the reference)
        float scale = (float)((double)T / (double)FIXED_FRAMES);
        float pos = ((float)f + 0.5f) * scale;
        int idx = (int)floorf(pos);
        if (idx < 0) idx = 0;
        if (idx > T - 1) idx = T - 1;
        const float* row = x + (size_t)idx * (N_LM * 3);
        for (int j = threadIdx.x; j < N_SEL * 3; j += RED_THREADS) {
            int l = j / 3;
            int comp = j - l * 3;
            float v = row[c_sel[l] * 3 + comp];
            out[f * (N_SEL * 3) + j] = (v == v) ? (v - meanf) * inv_std : 0.0f;
        }
    } else {
        // linear, align_corners=False
        float scale = (float)((double)T / (double)FIXED_FRAMES);
        float pos = ((float)f + 0.5f) * scale - 0.5f;
        pos = fminf(fmaxf(pos, 0.0f), (float)(T - 1));
        int i0 = (int)floorf(pos);
        int i1 = min(i0 + 1, T - 1);
        float w = pos - (float)i0;
        const float* row0 = x + (size_t)i0 * (N_LM * 3);
        const float* row1 = x + (size_t)i1 * (N_LM * 3);
        for (int j = threadIdx.x; j < N_SEL * 3; j += RED_THREADS) {
            int l = j / 3;
            int comp = j - l * 3;
            float v0 = row0[c_sel[l] * 3 + comp];
            float v1 = row1[c_sel[l] * 3 + comp];
            float y0 = (v0 == v0) ? (v0 - meanf) * inv_std : 0.0f;
            float y1 = (v1 == v1) ? (v1 - meanf) * inv_std : 0.0f;
            out[f * (N_SEL * 3) + j] = (1.0f - w) * y0 + w * y1;
        }
    }

    // ---------------- Phase 5: reset counters for next graph replay --------
    if (ticket == RED_BLOCKS - 1 && threadIdx.x == 0) {
        while (*(volatile int*)&g_ack < N_GATHER) __nanosleep(64);
        g_ack = 0;
        __threadfence();
        g_done = 0;
    }
}

extern "C" void kernel_launch(void* const* d_in, const int* in_sizes, int n_in,
                              void* d_out, int out_size) {
    const float* x = (const float*)d_in[0];
    float* out = (float*)d_out;

    long long ntotal = (long long)in_sizes[0];
    int T = (int)(ntotal / (N_LM * 3));
    long long nvec = ntotal >> 2;
    long long ntail = ntotal & 3;

    fused_kernel<<<RED_BLOCKS, RED_THREADS>>>((const float4*)x, nvec, x, ntail, out, T);
}